// round 1
// baseline (speedup 1.0000x reference)
#include <cuda_runtime.h>
#include <cstdint>

// BoundaryOperator: out[r, :] += val * feat[c, :]  (SpMM scatter, D=64 fp32)
//
// Inputs (metadata order):
//   d_in[0] simplex_features : float32 [NUM_E * 64]
//   d_in[1] boundary_values  : float32 [NNZ]
//   d_in[2] boundary_rows    : int32   [NNZ]
//   d_in[3] boundary_cols    : int32   [NNZ]
//   d_in[4] num_out          : int32   [1]   (device scalar; we use out_size instead)
// Output: float32 [NUM_V * 64]

#define D_FEAT   64
#define D_CHUNKS 16   // 64 floats = 16 x float4

__global__ void zero_out_kernel(float4* __restrict__ out4, int n4) {
    int i = blockIdx.x * blockDim.x + threadIdx.x;
    if (i < n4) out4[i] = make_float4(0.f, 0.f, 0.f, 0.f);
}

__global__ __launch_bounds__(256) void spmm_scatter_kernel(
    const float4* __restrict__ feat4,   // [NUM_E * 16]
    const float*  __restrict__ vals,    // [NNZ]
    const int*    __restrict__ rows,    // [NNZ]
    const int*    __restrict__ cols,    // [NNZ]
    float*        __restrict__ out,     // [NUM_V * 64]
    int nnz)
{
    int i = blockIdx.x * blockDim.x + threadIdx.x;
    int e = i >> 4;          // nonzero index
    if (e >= nnz) return;
    int chunk = i & 15;      // which float4 of the 64-float row

    // 16 consecutive threads share the same e -> these three loads hit the
    // same L1 lines (broadcast); cheap.
    int   r = rows[e];
    int   c = cols[e];
    float v = vals[e];

    // Coalesced: the 16 threads of this nnz read contiguous 256B.
    float4 f = feat4[(size_t)c * D_CHUNKS + chunk];

    float4 g;
    g.x = v * f.x;
    g.y = v * f.y;
    g.z = v * f.z;
    g.w = v * f.w;

    float* p = out + (size_t)r * D_FEAT + chunk * 4;   // 16B-aligned
    // Vectorized no-return global reduction (sm_90+): one REDG for 4 floats.
    asm volatile("red.global.add.v4.f32 [%0], {%1, %2, %3, %4};"
                 :: "l"(p), "f"(g.x), "f"(g.y), "f"(g.z), "f"(g.w)
                 : "memory");
}

extern "C" void kernel_launch(void* const* d_in, const int* in_sizes, int n_in,
                              void* d_out, int out_size) {
    const float4* feat4 = (const float4*)d_in[0];
    const float*  vals  = (const float*) d_in[1];
    const int*    rows  = (const int*)   d_in[2];
    const int*    cols  = (const int*)   d_in[3];
    float*        out   = (float*)       d_out;

    int nnz = in_sizes[1];

    // 1) zero the (poisoned) output
    int n4 = out_size / 4;   // number of float4s
    {
        int threads = 256;
        int blocks = (n4 + threads - 1) / threads;
        zero_out_kernel<<<blocks, threads>>>((float4*)out, n4);
    }

    // 2) scatter SpMM: one thread per (nnz, float4 chunk)
    {
        long long total = (long long)nnz * D_CHUNKS;
        int threads = 256;
        long long blocks = (total + threads - 1) / threads;
        spmm_scatter_kernel<<<(int)blocks, threads>>>(feat4, vals, rows, cols, out, nnz);
    }
}

// round 3
// speedup vs baseline: 1.2759x; 1.2759x over previous
#include <cuda_runtime.h>
#include <cstdint>

// BoundaryOperator: out[r,:] += val * feat[c,:]  (SpMM, D=64 fp32)
// Fixed-stride binning (no scan) -> gather with streaming output write.
// Overflow (>16 nnz in a row) handled by vectorized atomic scatter.

#define D_FEAT   64
#define K_MAX    16            // slots per row (128B slab of int2)
#define NV_CAP   524288        // max output rows supported by bin path
#define OVF_CAP  1048576       // overflow entries

__device__ int  g_counts[NV_CAP];
__device__ int2 g_bins[(size_t)NV_CAP * K_MAX];   // {col, float_bits(val)}
__device__ int4 g_ovf[OVF_CAP];                   // {row, col, valbits, pad}
__device__ int  g_ovf_count;

// ---------------- kernels ----------------

__global__ void zero_counts_kernel(int n) {
    int i = blockIdx.x * blockDim.x + threadIdx.x;
    if (i < n) g_counts[i] = 0;
    if (i == 0) g_ovf_count = 0;
}

__global__ __launch_bounds__(256) void bin_kernel(
    const int*   __restrict__ rows,
    const int*   __restrict__ cols,
    const float* __restrict__ vals,
    int nnz)
{
    int i = blockIdx.x * blockDim.x + threadIdx.x;
    if (i >= nnz) return;
    int r = rows[i];
    int c = cols[i];
    int vb = __float_as_int(vals[i]);
    int slot = atomicAdd(&g_counts[r], 1);
    if (slot < K_MAX) {
        g_bins[(size_t)r * K_MAX + slot] = make_int2(c, vb);
    } else {
        int o = atomicAdd(&g_ovf_count, 1);
        if (o < OVF_CAP) g_ovf[o] = make_int4(r, c, vb, 0);
    }
}

// one warp per output row; lane owns a float2 (32 lanes x 8B = 256B row)
__global__ __launch_bounds__(256) void gather_kernel(
    const float2* __restrict__ feat2,   // [NUM_E * 32]
    float2*       __restrict__ out2,    // [num_v * 32]
    int num_v)
{
    int warp = (blockIdx.x * blockDim.x + threadIdx.x) >> 5;
    int lane = threadIdx.x & 31;
    if (warp >= num_v) return;

    int n = g_counts[warp];              // broadcast load
    if (n > K_MAX) n = K_MAX;
    const int2* slab = &g_bins[(size_t)warp * K_MAX];

    float2 acc = make_float2(0.f, 0.f);
    #pragma unroll 4
    for (int j = 0; j < n; j++) {
        int2  b = slab[j];                           // broadcast, 128B slab
        float v = __int_as_float(b.y);
        float2 f = feat2[(size_t)b.x * 32 + lane];   // coalesced 256B gather
        acc.x = fmaf(v, f.x, acc.x);
        acc.y = fmaf(v, f.y, acc.y);
    }
    out2[(size_t)warp * 32 + lane] = acc;            // streaming full-line write
}

// overflow entries: vectorized no-return atomics (runs after gather)
__global__ __launch_bounds__(256) void overflow_kernel(
    const float4* __restrict__ feat4,   // [NUM_E * 16]
    float*        __restrict__ out)
{
    int total = g_ovf_count;
    if (total > OVF_CAP) total = OVF_CAP;
    for (int i = blockIdx.x * blockDim.x + threadIdx.x;
         i < total; i += gridDim.x * blockDim.x) {
        int4 e = g_ovf[i];
        float v = __int_as_float(e.z);
        float* p = out + (size_t)e.x * D_FEAT;
        const float4* f = feat4 + (size_t)e.y * 16;
        #pragma unroll
        for (int k = 0; k < 16; k++) {
            float4 t = f[k];
            asm volatile("red.global.add.v4.f32 [%0], {%1, %2, %3, %4};"
                         :: "l"(p + k * 4),
                            "f"(v * t.x), "f"(v * t.y), "f"(v * t.z), "f"(v * t.w)
                         : "memory");
        }
    }
}

// ---------------- fallback (proven R1 atomic path) ----------------

__global__ void zero_out_kernel(float4* __restrict__ out4, int n4) {
    int i = blockIdx.x * blockDim.x + threadIdx.x;
    if (i < n4) out4[i] = make_float4(0.f, 0.f, 0.f, 0.f);
}

__global__ __launch_bounds__(256) void spmm_scatter_kernel(
    const float4* __restrict__ feat4, const float* __restrict__ vals,
    const int* __restrict__ rows, const int* __restrict__ cols,
    float* __restrict__ out, int nnz)
{
    int i = blockIdx.x * blockDim.x + threadIdx.x;
    int e = i >> 4;
    if (e >= nnz) return;
    int chunk = i & 15;
    int   r = rows[e];
    int   c = cols[e];
    float v = vals[e];
    float4 f = feat4[(size_t)c * 16 + chunk];
    float* p = out + (size_t)r * D_FEAT + chunk * 4;
    asm volatile("red.global.add.v4.f32 [%0], {%1, %2, %3, %4};"
                 :: "l"(p), "f"(v * f.x), "f"(v * f.y), "f"(v * f.z), "f"(v * f.w)
                 : "memory");
}

extern "C" void kernel_launch(void* const* d_in, const int* in_sizes, int n_in,
                              void* d_out, int out_size) {
    const float* feat = (const float*)d_in[0];
    const float* vals = (const float*)d_in[1];
    const int*   rows = (const int*)  d_in[2];
    const int*   cols = (const int*)  d_in[3];
    float*       out  = (float*)      d_out;

    int nnz   = in_sizes[1];
    int num_v = out_size / D_FEAT;

    if (num_v > NV_CAP || num_v <= 0 || nnz <= 0) {
        int n4 = out_size / 4;
        zero_out_kernel<<<(n4 + 255) / 256, 256>>>((float4*)out, n4);
        if (nnz > 0) {
            long long total = (long long)nnz * 16;
            spmm_scatter_kernel<<<(int)((total + 255) / 256), 256>>>(
                (const float4*)feat, vals, rows, cols, out, nnz);
        }
        return;
    }

    zero_counts_kernel<<<(num_v + 255) / 256, 256>>>(num_v);
    bin_kernel<<<(nnz + 255) / 256, 256>>>(rows, cols, vals, nnz);

    long long gthreads = (long long)num_v * 32;
    gather_kernel<<<(int)((gthreads + 255) / 256), 256>>>(
        (const float2*)feat, (float2*)out, num_v);

    overflow_kernel<<<512, 256>>>((const float4*)feat, out);
}

// round 4
// speedup vs baseline: 1.3782x; 1.0801x over previous
#include <cuda_runtime.h>
#include <cstdint>

// BoundaryOperator: out[r,:] += val * feat[c,:]  (SpMM, D=64 fp32)
// Fixed-stride binning (no scan) -> gather with slab prefetch (high MLP)
// and streaming output write. Overflow (>16 nnz/row) via vectorized atomics.

#define D_FEAT   64
#define K_MAX    16            // slots per row (128B slab of int2)
#define NV_CAP   524288        // max output rows supported by bin path
#define OVF_CAP  1048576       // overflow entries

__device__ int  g_counts[NV_CAP];
__device__ int2 g_bins[(size_t)NV_CAP * K_MAX];   // {col, float_bits(val)}
__device__ int4 g_ovf[OVF_CAP];                   // {row, col, valbits, pad}
__device__ int  g_ovf_count;

// ---------------- kernels ----------------

__global__ void zero_counts_kernel(int n) {
    int i = blockIdx.x * blockDim.x + threadIdx.x;
    if (i < n) g_counts[i] = 0;
    if (i == 0) g_ovf_count = 0;
}

__global__ __launch_bounds__(256) void bin_kernel(
    const int*   __restrict__ rows,
    const int*   __restrict__ cols,
    const float* __restrict__ vals,
    int nnz)
{
    int i = blockIdx.x * blockDim.x + threadIdx.x;
    if (i >= nnz) return;
    int   r  = __ldcs(&rows[i]);        // read-once streams: don't pollute L2
    int   c  = __ldcs(&cols[i]);
    float v  = __ldcs(&vals[i]);
    int slot = atomicAdd(&g_counts[r], 1);
    if (slot < K_MAX) {
        g_bins[(size_t)r * K_MAX + slot] = make_int2(c, __float_as_int(v));
    } else {
        int o = atomicAdd(&g_ovf_count, 1);
        if (o < OVF_CAP) g_ovf[o] = make_int4(r, c, __float_as_int(v), 0);
    }
}

// one warp per output row; lane owns a float2 (32 lanes x 8B = 256B row).
// Slab is prefetched by one coalesced load + shuffles so the up-to-16
// feature LDGs are independent (high MLP), then accumulated.
__global__ __launch_bounds__(256) void gather_kernel(
    const float2* __restrict__ feat2,   // [NUM_E * 32]
    float2*       __restrict__ out2,    // [num_v * 32]
    int num_v)
{
    int warp = (blockIdx.x * blockDim.x + threadIdx.x) >> 5;
    int lane = threadIdx.x & 31;
    if (warp >= num_v) return;

    int n = g_counts[warp];              // broadcast load
    if (n > K_MAX) n = K_MAX;
    const int2* slab = &g_bins[(size_t)warp * K_MAX];

    // one coalesced 128B slab read: lane j holds entry j
    int2 mine = make_int2(0, 0);
    if (lane < n) mine = slab[lane];

    // broadcast entries to all lanes (fixed-count, fully unrolled)
    int   cs[K_MAX];
    float vs[K_MAX];
    #pragma unroll
    for (int j = 0; j < K_MAX; j++) {
        cs[j] = __shfl_sync(0xffffffffu, mine.x, j);
        vs[j] = __int_as_float(__shfl_sync(0xffffffffu, mine.y, j));
    }

    // predicated, unrolled: all feature loads independent -> MLP = n
    float2 acc = make_float2(0.f, 0.f);
    #pragma unroll
    for (int j = 0; j < K_MAX; j++) {
        if (j < n) {
            float2 f = feat2[(size_t)cs[j] * 32 + lane];
            acc.x = fmaf(vs[j], f.x, acc.x);
            acc.y = fmaf(vs[j], f.y, acc.y);
        }
    }

    // streaming (evict-first) full-line write: keep features resident in L2
    float2* p = out2 + (size_t)warp * 32 + lane;
    asm volatile("st.global.cs.v2.f32 [%0], {%1, %2};"
                 :: "l"(p), "f"(acc.x), "f"(acc.y) : "memory");
}

// overflow entries: vectorized no-return atomics (runs after gather)
__global__ __launch_bounds__(256) void overflow_kernel(
    const float4* __restrict__ feat4,   // [NUM_E * 16]
    float*        __restrict__ out)
{
    int total = g_ovf_count;
    if (total > OVF_CAP) total = OVF_CAP;
    for (int i = blockIdx.x * blockDim.x + threadIdx.x;
         i < total; i += gridDim.x * blockDim.x) {
        int4 e = g_ovf[i];
        float v = __int_as_float(e.z);
        float* p = out + (size_t)e.x * D_FEAT;
        const float4* f = feat4 + (size_t)e.y * 16;
        #pragma unroll
        for (int k = 0; k < 16; k++) {
            float4 t = f[k];
            asm volatile("red.global.add.v4.f32 [%0], {%1, %2, %3, %4};"
                         :: "l"(p + k * 4),
                            "f"(v * t.x), "f"(v * t.y), "f"(v * t.z), "f"(v * t.w)
                         : "memory");
        }
    }
}

// ---------------- fallback (proven R1 atomic path) ----------------

__global__ void zero_out_kernel(float4* __restrict__ out4, int n4) {
    int i = blockIdx.x * blockDim.x + threadIdx.x;
    if (i < n4) out4[i] = make_float4(0.f, 0.f, 0.f, 0.f);
}

__global__ __launch_bounds__(256) void spmm_scatter_kernel(
    const float4* __restrict__ feat4, const float* __restrict__ vals,
    const int* __restrict__ rows, const int* __restrict__ cols,
    float* __restrict__ out, int nnz)
{
    int i = blockIdx.x * blockDim.x + threadIdx.x;
    int e = i >> 4;
    if (e >= nnz) return;
    int chunk = i & 15;
    int   r = rows[e];
    int   c = cols[e];
    float v = vals[e];
    float4 f = feat4[(size_t)c * 16 + chunk];
    float* p = out + (size_t)r * D_FEAT + chunk * 4;
    asm volatile("red.global.add.v4.f32 [%0], {%1, %2, %3, %4};"
                 :: "l"(p), "f"(v * f.x), "f"(v * f.y), "f"(v * f.z), "f"(v * f.w)
                 : "memory");
}

extern "C" void kernel_launch(void* const* d_in, const int* in_sizes, int n_in,
                              void* d_out, int out_size) {
    const float* feat = (const float*)d_in[0];
    const float* vals = (const float*)d_in[1];
    const int*   rows = (const int*)  d_in[2];
    const int*   cols = (const int*)  d_in[3];
    float*       out  = (float*)      d_out;

    int nnz   = in_sizes[1];
    int num_v = out_size / D_FEAT;

    if (num_v > NV_CAP || num_v <= 0 || nnz <= 0) {
        int n4 = out_size / 4;
        zero_out_kernel<<<(n4 + 255) / 256, 256>>>((float4*)out, n4);
        if (nnz > 0) {
            long long total = (long long)nnz * 16;
            spmm_scatter_kernel<<<(int)((total + 255) / 256), 256>>>(
                (const float4*)feat, vals, rows, cols, out, nnz);
        }
        return;
    }

    zero_counts_kernel<<<(num_v + 255) / 256, 256>>>(num_v);
    bin_kernel<<<(nnz + 255) / 256, 256>>>(rows, cols, vals, nnz);

    long long gthreads = (long long)num_v * 32;
    gather_kernel<<<(int)((gthreads + 255) / 256), 256>>>(
        (const float2*)feat, (float2*)out, num_v);

    overflow_kernel<<<48, 256>>>((const float4*)feat, out);
}